// round 2
// baseline (speedup 1.0000x reference)
#include <cuda_runtime.h>
#include <cuda_bf16.h>

// Gps: 2-layer graph encoder.
//   agg0 = 0.5 * adj1 @ f1                          [16384,256]
//   h    = lrelu([gather(feat,seed) | agg0] @ W1^T) [16384,256]
//   aggm = 0.125 * (sum of 4-row groups of adj2) @ f2   (== 0.5*mean trick)
//   emb  = lrelu([h | aggm] @ W2^T)                 [16384,256]  -> d_out
//
// All GEMMs: SIMT fp32, 128x128x16 tiles, 8x8 micro-tile using packed
// fma.rn.f32x2 (2 FMA/lane/instr) for 2x FFMA throughput.

#define BM 128
#define BN 128
#define BK 16
#define APAD 4
#define BPAD 4

#define N_SEED 16384
#define NOUT 256

__device__ float g_agg0[N_SEED * 256];
__device__ float g_aggm[N_SEED * 256];
__device__ float g_h[N_SEED * 256];

__device__ __forceinline__ unsigned long long splat2(float a) {
    unsigned long long r;
    asm("mov.b64 %0, {%1, %1};" : "=l"(r) : "f"(a));
    return r;
}
__device__ __forceinline__ void fma2(unsigned long long& acc,
                                     unsigned long long a,
                                     unsigned long long b) {
    asm("fma.rn.f32x2 %0, %1, %2, %0;" : "+l"(acc) : "l"(a), "l"(b));
}
__device__ __forceinline__ float2 unpack2(unsigned long long v) {
    float2 r;
    asm("mov.b64 {%0, %1}, %2;" : "=f"(r.x), "=f"(r.y) : "l"(v));
    return r;
}

// ---------------------------------------------------------------------------
// Big GEMM: C[M,256] = scale * A' @ B
//   AVG4=false: A' = A  (A is [M,K] row-major)
//   AVG4=true : A'[m,:] = sum of rows 4m..4m+3 of A  (A is [4M,K])
// B is [K,256] row-major. M = 16384 (grid fixed), no bounds checks needed.
// ---------------------------------------------------------------------------
template <bool AVG4>
__global__ void __launch_bounds__(256, 2)
gemm_big(const float* __restrict__ A, const float* __restrict__ B,
         float* __restrict__ C, int K, float scale) {
    __shared__ __align__(16) float As[BK][BM + APAD];
    __shared__ __align__(16) float Bs[BK][BN + BPAD];

    const int tid = threadIdx.x;
    const int bm = blockIdx.x, bn = blockIdx.y;
    const int tx = tid & 15, ty = tid >> 4;

    const int a_row = tid >> 2;         // 0..63
    const int a_col = (tid & 3) << 2;   // 0,4,8,12
    const int b_row = tid >> 5;         // 0..7
    const int b_col = (tid & 31) << 2;  // 0..124

    unsigned long long acc[8][4];
#pragma unroll
    for (int i = 0; i < 8; i++)
#pragma unroll
        for (int j = 0; j < 4; j++) acc[i][j] = 0ull;

    for (int k0 = 0; k0 < K; k0 += BK) {
        // --- load A tile (transposed into SMEM) ---
#pragma unroll
        for (int r = 0; r < 2; r++) {
            const int m = bm * BM + a_row + r * 64;
            float4 v;
            if (AVG4) {
                const float* p = A + (size_t)m * 4 * K + k0 + a_col;
                float4 v0 = *(const float4*)p;
                float4 v1 = *(const float4*)(p + K);
                float4 v2 = *(const float4*)(p + 2 * (size_t)K);
                float4 v3 = *(const float4*)(p + 3 * (size_t)K);
                v.x = (v0.x + v1.x) + (v2.x + v3.x);
                v.y = (v0.y + v1.y) + (v2.y + v3.y);
                v.z = (v0.z + v1.z) + (v2.z + v3.z);
                v.w = (v0.w + v1.w) + (v2.w + v3.w);
            } else {
                v = *(const float4*)(A + (size_t)m * K + k0 + a_col);
            }
            As[a_col + 0][a_row + r * 64] = v.x;
            As[a_col + 1][a_row + r * 64] = v.y;
            As[a_col + 2][a_row + r * 64] = v.z;
            As[a_col + 3][a_row + r * 64] = v.w;
        }
        // --- load B tile ---
#pragma unroll
        for (int r = 0; r < 2; r++) {
            const int k = b_row + r * 8;
            *(float4*)&Bs[k][b_col] =
                *(const float4*)(B + (size_t)(k0 + k) * NOUT + bn * BN + b_col);
        }
        __syncthreads();

#pragma unroll
        for (int kk = 0; kk < BK; kk++) {
            float a[8];
            *(float4*)&a[0] = *(const float4*)&As[kk][ty * 4];
            *(float4*)&a[4] = *(const float4*)&As[kk][64 + ty * 4];
            unsigned long long b[4];
            {
                ulonglong2 t0 = *(const ulonglong2*)&Bs[kk][tx * 4];
                ulonglong2 t1 = *(const ulonglong2*)&Bs[kk][64 + tx * 4];
                b[0] = t0.x; b[1] = t0.y; b[2] = t1.x; b[3] = t1.y;
            }
#pragma unroll
            for (int i = 0; i < 8; i++) {
                unsigned long long a2 = splat2(a[i]);
#pragma unroll
                for (int j = 0; j < 4; j++) fma2(acc[i][j], a2, b[j]);
            }
        }
        __syncthreads();
    }

#pragma unroll
    for (int i = 0; i < 8; i++) {
        const int m = bm * BM + ((i < 4) ? (ty * 4 + i) : (64 + ty * 4 + i - 4));
#pragma unroll
        for (int j = 0; j < 4; j++) {
            const int n =
                bn * BN + ((j < 2) ? (tx * 4 + j * 2) : (64 + tx * 4 + (j - 2) * 2));
            float2 v = unpack2(acc[i][j]);
            v.x *= scale;
            v.y *= scale;
            *(float2*)(C + (size_t)m * NOUT + n) = v;
        }
    }
}

// ---------------------------------------------------------------------------
// Concat GEMM: C[M,256] = leakyrelu( [A1 | A2] @ W^T ), K = 512.
//   A1: [*,256]; if GATHER, row m comes from A1[seed[m]]. A2: [M,256].
//   W: [256,512] row-major; B[k][n] = W[n][k].
// ---------------------------------------------------------------------------
template <bool GATHER>
__global__ void __launch_bounds__(256, 2)
gemm_cat(const float* __restrict__ A1, const float* __restrict__ A2,
         const float* __restrict__ W, const int* __restrict__ seed,
         float* __restrict__ C) {
    __shared__ __align__(16) float As[BK][BM + APAD];
    __shared__ __align__(16) float Bs[BK][BN + BPAD];

    const int tid = threadIdx.x;
    const int bm = blockIdx.x, bn = blockIdx.y;
    const int tx = tid & 15, ty = tid >> 4;

    const int a_row = tid >> 2;
    const int a_col = (tid & 3) << 2;
    const int w_n = tid >> 2;          // 0..63
    const int w_k = (tid & 3) << 2;    // 0,4,8,12

    // hoist gather indices
    int src_row[2];
#pragma unroll
    for (int r = 0; r < 2; r++) {
        const int m = bm * BM + a_row + r * 64;
        src_row[r] = GATHER ? seed[m] : m;
    }

    unsigned long long acc[8][4];
#pragma unroll
    for (int i = 0; i < 8; i++)
#pragma unroll
        for (int j = 0; j < 4; j++) acc[i][j] = 0ull;

    for (int k0 = 0; k0 < 512; k0 += BK) {
#pragma unroll
        for (int r = 0; r < 2; r++) {
            const int m = bm * BM + a_row + r * 64;
            float4 v;
            if (k0 < 256) {
                v = *(const float4*)(A1 + (size_t)src_row[r] * 256 + k0 + a_col);
            } else {
                v = *(const float4*)(A2 + (size_t)m * 256 + (k0 - 256) + a_col);
            }
            As[a_col + 0][a_row + r * 64] = v.x;
            As[a_col + 1][a_row + r * 64] = v.y;
            As[a_col + 2][a_row + r * 64] = v.z;
            As[a_col + 3][a_row + r * 64] = v.w;
        }
        // B tile (transposed load from W)
#pragma unroll
        for (int r = 0; r < 2; r++) {
            const int n = w_n + r * 64;
            float4 w =
                *(const float4*)(W + (size_t)(bn * BN + n) * 512 + k0 + w_k);
            Bs[w_k + 0][n] = w.x;
            Bs[w_k + 1][n] = w.y;
            Bs[w_k + 2][n] = w.z;
            Bs[w_k + 3][n] = w.w;
        }
        __syncthreads();

#pragma unroll
        for (int kk = 0; kk < BK; kk++) {
            float a[8];
            *(float4*)&a[0] = *(const float4*)&As[kk][ty * 4];
            *(float4*)&a[4] = *(const float4*)&As[kk][64 + ty * 4];
            unsigned long long b[4];
            {
                ulonglong2 t0 = *(const ulonglong2*)&Bs[kk][tx * 4];
                ulonglong2 t1 = *(const ulonglong2*)&Bs[kk][64 + tx * 4];
                b[0] = t0.x; b[1] = t0.y; b[2] = t1.x; b[3] = t1.y;
            }
#pragma unroll
            for (int i = 0; i < 8; i++) {
                unsigned long long a2 = splat2(a[i]);
#pragma unroll
                for (int j = 0; j < 4; j++) fma2(acc[i][j], a2, b[j]);
            }
        }
        __syncthreads();
    }

#pragma unroll
    for (int i = 0; i < 8; i++) {
        const int m = bm * BM + ((i < 4) ? (ty * 4 + i) : (64 + ty * 4 + i - 4));
#pragma unroll
        for (int j = 0; j < 4; j++) {
            const int n =
                bn * BN + ((j < 2) ? (tx * 4 + j * 2) : (64 + tx * 4 + (j - 2) * 2));
            float2 v = unpack2(acc[i][j]);
            v.x = (v.x >= 0.0f) ? v.x : 0.01f * v.x;
            v.y = (v.y >= 0.0f) ? v.y : 0.01f * v.y;
            *(float2*)(C + (size_t)m * NOUT + n) = v;
        }
    }
}

extern "C" void kernel_launch(void* const* d_in, const int* in_sizes, int n_in,
                              void* d_out, int out_size) {
    const float* feature_matrix = (const float*)d_in[0];  // [100000,256]
    const float* adj1 = (const float*)d_in[1];            // [16384,4096]
    const float* f1 = (const float*)d_in[2];              // [4096,256]
    const float* adj2 = (const float*)d_in[3];            // [65536,2048]
    const float* f2 = (const float*)d_in[4];              // [2048,256]
    const float* W1 = (const float*)d_in[5];              // [256,512]
    const float* W2 = (const float*)d_in[6];              // [256,512]
    const int* seed = (const int*)d_in[7];                // [16384] int32
    float* out = (float*)d_out;                           // [16384,256]

    float *agg0, *aggm, *h;
    cudaGetSymbolAddress((void**)&agg0, g_agg0);
    cudaGetSymbolAddress((void**)&aggm, g_aggm);
    cudaGetSymbolAddress((void**)&h, g_h);

    dim3 grid(N_SEED / BM, NOUT / BN);  // (128, 2)
    dim3 blk(256);

    // agg0 = 0.5 * adj1 @ f1
    gemm_big<false><<<grid, blk>>>(adj1, f1, agg0, 4096, 0.5f);
    // aggm = 0.125 * (4-row-sum of adj2) @ f2   (= 0.5 * mean, folded)
    gemm_big<true><<<grid, blk>>>(adj2, f2, aggm, 2048, 0.125f);
    // h = lrelu([gather(feat,seed) | agg0] @ W1^T)
    gemm_cat<true><<<grid, blk>>>(feature_matrix, agg0, W1, seed, h);
    // emb = lrelu([h | aggm] @ W2^T)
    gemm_cat<false><<<grid, blk>>>(h, aggm, W2, nullptr, out);
}

// round 5
// speedup vs baseline: 1.6536x; 1.6536x over previous
#include <cuda_runtime.h>
#include <cuda_bf16.h>
#include <cstdint>

// ============================================================================
// Gps via mma.sync m16n8k8 tf32 (HMMA; tcgen05 rejected by compute_103 lowering).
// Precision: A operands RN-rounded to tf32 (cvt.rna in the fill / producers);
// B operands exact hi/lo split (hi tf32-representable, lo residual).
//   Acat1 = [rn(feat[seed]) | rn(0.5 * adj1 @ f1)]            [16384, 512]
//   Acat2 = [rn(lrelu(Acat1 @ W1^T)) | rn(0.125*fold4(adj2) @ f2)]
//   out   = lrelu(Acat2 @ W2^T)                               [16384, 256]
// fold4 (sum of 4 consecutive rows of adj2) fused into GEMM2's A fill.
// CTA tile 128x128x32, 8 warps (2m x 4n), 2-stage pipeline:
//   B hi/lo via cp.async, A via LDG+rn+STS (reg double-buffered).
// ============================================================================

#define STAGE 55296               // A 18432 | Bhi 18432 | Blo 18432
#define SMEM_TOTAL (2 * STAGE)    // 110592

__device__ float g_Acat1[16384 * 512];
__device__ float g_Acat2[16384 * 512];
__device__ float g_f1s[2][4096 * 256];
__device__ float g_f2s[2][2048 * 256];
__device__ float g_W1s[2][256 * 512];
__device__ float g_W2s[2][256 * 512];

__device__ __forceinline__ uint32_t smem_u32(const void* p) {
    uint32_t a;
    asm("{ .reg .u64 t; cvta.to.shared.u64 t, %1; cvt.u32.u64 %0, t; }" : "=r"(a) : "l"(p));
    return a;
}
__device__ __forceinline__ void cpa16(uint32_t dst, const void* src) {
    asm volatile("cp.async.cg.shared.global [%0], [%1], 16;" :: "r"(dst), "l"(src));
}
__device__ __forceinline__ float rn_tf32(float v) {
    uint32_t u;
    asm("cvt.rna.tf32.f32 %0, %1;" : "=r"(u) : "f"(v));
    return __uint_as_float(u);
}
__device__ __forceinline__ float4 rn4(float4 v) {
    v.x = rn_tf32(v.x); v.y = rn_tf32(v.y); v.z = rn_tf32(v.z); v.w = rn_tf32(v.w);
    return v;
}
__device__ __forceinline__ void mma_tf32(float* c, const uint32_t* a, const uint32_t* b) {
    asm volatile(
        "mma.sync.aligned.m16n8k8.row.col.f32.tf32.tf32.f32 "
        "{%0,%1,%2,%3}, {%4,%5,%6,%7}, {%8,%9}, {%0,%1,%2,%3};"
        : "+f"(c[0]), "+f"(c[1]), "+f"(c[2]), "+f"(c[3])
        : "r"(a[0]), "r"(a[1]), "r"(a[2]), "r"(a[3]), "r"(b[0]), "r"(b[1]));
}

// ============================================================================
// C[16384,256] = act(scale * A' @ B'), one 128x128 tile per CTA.
//   A': FOLD==4 ? 4-row-group sums of A[65536,K] : A[16384,K]  (row-major)
//   B' hi/lo: BNKL ? [256,K] row-major (W layout) : [K,256] row-major (f layout)
// ============================================================================
template <int FOLD, int BNKL>
__global__ void __launch_bounds__(256, 2)
gemm_mma(const float* __restrict__ A, const float* __restrict__ Bhi,
         const float* __restrict__ Blo, float* __restrict__ C,
         int ldc, int K, float scale, int do_lrelu, int rn_out) {
    extern __shared__ char smem[];
    const uint32_t sb = smem_u32(smem);
    const int tid = threadIdx.x;
    const int l = tid & 31, wid = tid >> 5;
    const int wm = wid & 1, wn = wid >> 1;      // 2(m) x 4(n) warps
    const int bm = blockIdx.x, bn = blockIdx.y;
    const int NK = K >> 5;

    float acc[4][4][4];
#pragma unroll
    for (int mt = 0; mt < 4; mt++)
#pragma unroll
        for (int nt = 0; nt < 4; nt++)
#pragma unroll
            for (int i = 0; i < 4; i++) acc[mt][nt][i] = 0.f;

    // per-thread A granules: 4 x (row = g>>3, q = g&7), g = tid + j*256
    const int ar_row[1] = {0};
    (void)ar_row;

    auto ldgA = [&](int kc, float4* r) {
        const int k0 = kc << 5;
#pragma unroll
        for (int j = 0; j < 4; j++) {
            const int g = tid + j * 256;
            const int row = g >> 3, q = g & 7;
            if (FOLD == 1) {
                r[j] = rn4(*(const float4*)(A + (size_t)(bm * 128 + row) * K + k0 + q * 4));
            } else {
                const float4* p = (const float4*)(A + (size_t)(bm * 128 + row) * 4 * K +
                                                  k0 + q * 4);
                const size_t rs = (size_t)K >> 2;
                float4 v0 = p[0], v1 = p[rs], v2 = p[2 * rs], v3 = p[3 * rs];
                float4 v;
                v.x = (v0.x + v1.x) + (v2.x + v3.x);
                v.y = (v0.y + v1.y) + (v2.y + v3.y);
                v.z = (v0.z + v1.z) + (v2.z + v3.z);
                v.w = (v0.w + v1.w) + (v2.w + v3.w);
                r[j] = rn4(v);
            }
        }
    };
    auto stsA = [&](const float4* r, int s) {
#pragma unroll
        for (int j = 0; j < 4; j++) {
            const int g = tid + j * 256;
            const int row = g >> 3, q = g & 7;
            *(float4*)(smem + s * STAGE + row * 144 + q * 16) = r[j];
        }
    };
    auto fillB = [&](int kc, int s) {
        const uint32_t bh = sb + s * STAGE + 18432;
        const uint32_t bl = bh + 18432;
        const int k0 = kc << 5;
        if (!BNKL) {  // [K,256] -> SMEM [32 k][136 n-stride]
#pragma unroll
            for (int j = 0; j < 4; j++) {
                const int g = tid + j * 256;
                const int k = g >> 5, nq = g & 31;
                const size_t off = (size_t)(k0 + k) * 256 + bn * 128 + nq * 4;
                const uint32_t so = k * 544 + nq * 16;
                cpa16(bh + so, Bhi + off);
                cpa16(bl + so, Blo + off);
            }
        } else {      // [256,K] -> SMEM [128 n][36 k-stride]
#pragma unroll
            for (int j = 0; j < 4; j++) {
                const int g = tid + j * 256;
                const int row = g >> 3, q = g & 7;
                const size_t off = (size_t)(bn * 128 + row) * K + k0 + q * 4;
                const uint32_t so = row * 144 + q * 16;
                cpa16(bh + so, Bhi + off);
                cpa16(bl + so, Blo + off);
            }
        }
    };

    // prologue: stage 0
    fillB(0, 0);
    asm volatile("cp.async.commit_group;" ::: "memory");
    {
        float4 a0[4];
        ldgA(0, a0);
        stsA(a0, 0);
    }

    for (int k = 0; k < NK; k++) {
        const int s = k & 1;
        __syncthreads();                          // compute(k-1) done; stage s^1 free
        float4 ar2[4];
        if (k + 1 < NK) {
            fillB(k + 1, s ^ 1);
            asm volatile("cp.async.commit_group;" ::: "memory");
            ldgA(k + 1, ar2);                     // LDGs fly during compute(k)
            asm volatile("cp.async.wait_group 1;" ::: "memory");
        } else {
            asm volatile("cp.async.wait_group 0;" ::: "memory");
        }
        __syncthreads();                          // stage s (B cp.async + A STS) visible

        const float* As = (const float*)(smem + s * STAGE);
        const float* Bh = (const float*)(smem + s * STAGE + 18432);
        const float* Bl = (const float*)(smem + s * STAGE + 36864);
#pragma unroll
        for (int ks = 0; ks < 4; ks++) {
            uint32_t a[4][4], bh[4][2], bl[4][2];
#pragma unroll
            for (int mt = 0; mt < 4; mt++) {
                const int r = wm * 64 + mt * 16 + (l >> 2);
                const int c = ks * 8 + (l & 3);
                a[mt][0] = __float_as_uint(As[r * 36 + c]);
                a[mt][1] = __float_as_uint(As[(r + 8) * 36 + c]);
                a[mt][2] = __float_as_uint(As[r * 36 + c + 4]);
                a[mt][3] = __float_as_uint(As[(r + 8) * 36 + c + 4]);
            }
#pragma unroll
            for (int nt = 0; nt < 4; nt++) {
                const int n = wn * 32 + nt * 8 + (l >> 2);
                const int kk = ks * 8 + (l & 3);
                if (!BNKL) {
                    bh[nt][0] = __float_as_uint(Bh[kk * 136 + n]);
                    bh[nt][1] = __float_as_uint(Bh[(kk + 4) * 136 + n]);
                    bl[nt][0] = __float_as_uint(Bl[kk * 136 + n]);
                    bl[nt][1] = __float_as_uint(Bl[(kk + 4) * 136 + n]);
                } else {
                    bh[nt][0] = __float_as_uint(Bh[n * 36 + kk]);
                    bh[nt][1] = __float_as_uint(Bh[n * 36 + kk + 4]);
                    bl[nt][0] = __float_as_uint(Bl[n * 36 + kk]);
                    bl[nt][1] = __float_as_uint(Bl[n * 36 + kk + 4]);
                }
            }
#pragma unroll
            for (int mt = 0; mt < 4; mt++)
#pragma unroll
                for (int nt = 0; nt < 4; nt++) {
                    mma_tf32(acc[mt][nt], a[mt], bh[nt]);
                    mma_tf32(acc[mt][nt], a[mt], bl[nt]);
                }
        }
        if (k + 1 < NK) stsA(ar2, s ^ 1);         // after compute; hidden by MMA latency
    }

    // epilogue
#pragma unroll
    for (int mt = 0; mt < 4; mt++) {
        const int r0 = bm * 128 + wm * 64 + mt * 16 + (l >> 2);
#pragma unroll
        for (int nt = 0; nt < 4; nt++) {
            const int c0 = bn * 128 + wn * 32 + nt * 8 + 2 * (l & 3);
#pragma unroll
            for (int h = 0; h < 2; h++) {
                float2 v;
                v.x = acc[mt][nt][2 * h + 0] * scale;
                v.y = acc[mt][nt][2 * h + 1] * scale;
                if (do_lrelu) {
                    v.x = (v.x >= 0.f) ? v.x : 0.01f * v.x;
                    v.y = (v.y >= 0.f) ? v.y : 0.01f * v.y;
                }
                if (rn_out) { v.x = rn_tf32(v.x); v.y = rn_tf32(v.y); }
                *(float2*)(C + (size_t)(r0 + h * 8) * ldc + c0) = v;
            }
        }
    }
}

// exact tf32 split: hi = top-10-mantissa part (tf32-representable), lo = v - hi
__global__ void esplit(const float* __restrict__ in, float* __restrict__ hi,
                       float* __restrict__ lo) {
    const int i = blockIdx.x * 256 + threadIdx.x;
    const float v = in[i];
    const float h = __uint_as_float(__float_as_uint(v) & 0xFFFFE000u);
    hi[i] = h;
    lo[i] = v - h;
}

// Acat1[m, 0:256] = rn_tf32(feature_matrix[seed[m], :])
__global__ void gatherk(const float4* __restrict__ feat, const int* __restrict__ seed,
                        float4* __restrict__ acat) {
    const int idx = blockIdx.x * 256 + threadIdx.x;   // 16384 * 64
    const int m = idx >> 6, q = idx & 63;
    acat[(size_t)m * 128 + q] = rn4(feat[(size_t)seed[m] * 64 + q]);
}

extern "C" void kernel_launch(void* const* d_in, const int* in_sizes, int n_in,
                              void* d_out, int out_size) {
    const float* feat = (const float*)d_in[0];   // [100000,256]
    const float* adj1 = (const float*)d_in[1];   // [16384,4096]
    const float* f1 = (const float*)d_in[2];     // [4096,256]
    const float* adj2 = (const float*)d_in[3];   // [65536,2048]
    const float* f2 = (const float*)d_in[4];     // [2048,256]
    const float* W1 = (const float*)d_in[5];     // [256,512]
    const float* W2 = (const float*)d_in[6];     // [256,512]
    const int* seed = (const int*)d_in[7];       // [16384]
    float* out = (float*)d_out;                  // [16384,256]

    float *Acat1, *Acat2, *f1s, *f2s, *W1s, *W2s;
    cudaGetSymbolAddress((void**)&Acat1, g_Acat1);
    cudaGetSymbolAddress((void**)&Acat2, g_Acat2);
    cudaGetSymbolAddress((void**)&f1s, g_f1s);
    cudaGetSymbolAddress((void**)&f2s, g_f2s);
    cudaGetSymbolAddress((void**)&W1s, g_W1s);
    cudaGetSymbolAddress((void**)&W2s, g_W2s);

    cudaFuncSetAttribute(gemm_mma<1, 0>, cudaFuncAttributeMaxDynamicSharedMemorySize, SMEM_TOTAL);
    cudaFuncSetAttribute(gemm_mma<4, 0>, cudaFuncAttributeMaxDynamicSharedMemorySize, SMEM_TOTAL);
    cudaFuncSetAttribute(gemm_mma<1, 1>, cudaFuncAttributeMaxDynamicSharedMemorySize, SMEM_TOTAL);

    // B-operand exact splits
    esplit<<<4096, 256>>>(f1, f1s, f1s + 4096 * 256);
    esplit<<<2048, 256>>>(f2, f2s, f2s + 2048 * 256);
    esplit<<<512, 256>>>(W1, W1s, W1s + 256 * 512);
    esplit<<<512, 256>>>(W2, W2s, W2s + 256 * 512);
    // Acat1[:,0:256] = rn(feat[seed])
    gatherk<<<4096, 256>>>((const float4*)feat, seed, (float4*)Acat1);

    dim3 grid(128, 2), blk(256);
    // Acat1[:,256:512] = rn(0.5 * adj1 @ f1)
    gemm_mma<1, 0><<<grid, blk, SMEM_TOTAL>>>(adj1, f1s, f1s + 4096 * 256,
                                              Acat1 + 256, 512, 4096, 0.5f, 0, 1);
    // Acat2[:,256:512] = rn(0.125 * fold4(adj2) @ f2)
    gemm_mma<4, 0><<<grid, blk, SMEM_TOTAL>>>(adj2, f2s, f2s + 2048 * 256,
                                              Acat2 + 256, 512, 2048, 0.125f, 0, 1);
    // Acat2[:,0:256] = rn(lrelu(Acat1 @ W1^T))
    gemm_mma<1, 1><<<grid, blk, SMEM_TOTAL>>>(Acat1, W1s, W1s + 256 * 512,
                                              Acat2, 512, 512, 1.0f, 1, 1);
    // out = lrelu(Acat2 @ W2^T)
    gemm_mma<1, 1><<<grid, blk, SMEM_TOTAL>>>(Acat2, W2s, W2s + 256 * 512,
                                              out, 256, 512, 1.0f, 1, 0);
}

// round 6
// speedup vs baseline: 1.9760x; 1.1950x over previous
#include <cuda_runtime.h>
#include <cuda_bf16.h>
#include <cstdint>

// ============================================================================
// Gps via mma.sync m16n8k16 bf16 3-term split (HMMA bf16 = 2x tf32 rate).
//   a = a_hi + a_lo, b = b_hi + b_lo (bf16 RN splits);
//   acc += a_hi*b_hi + a_lo*b_hi + a_hi*b_lo   (dropped a_lo*b_lo ~ 2^-18)
// A split happens in the tile fill (LDG fp32 -> bf16 hi/lo STS, no extra DRAM);
// fold4 (4-row sums of adj2) fused into GEMM2's A fill.
// B operands pre-split n-major [256, K] bf16 by prep kernels.
// CTA tile 128x128x32, 8 warps (2m x 4n), 2-stage pipeline, grid(bn=2, bm=128)
// so bn-pairs are L2-co-resident (adj read from DRAM once).
// ============================================================================

#define STAGE 40960              // Ah 10240 | Al 10240 | Bh 10240 | Bl 10240
#define SMEM_TOTAL (2 * STAGE)   // 81920
#define OFF_AH 0
#define OFF_AL 10240
#define OFF_BH 20480
#define OFF_BL 30720
#define LDW 20                   // row stride in 4B words (40 bf16 = 80B)

__device__ float g_Acat1[16384 * 512];
__device__ float g_Acat2[16384 * 512];
__device__ __nv_bfloat16 g_f1b[2][256 * 4096];
__device__ __nv_bfloat16 g_f2b[2][256 * 2048];
__device__ __nv_bfloat16 g_W1b[2][256 * 512];
__device__ __nv_bfloat16 g_W2b[2][256 * 512];

__device__ __forceinline__ uint32_t smem_u32(const void* p) {
    uint32_t a;
    asm("{ .reg .u64 t; cvta.to.shared.u64 t, %1; cvt.u32.u64 %0, t; }" : "=r"(a) : "l"(p));
    return a;
}
__device__ __forceinline__ void cpa16(uint32_t dst, const void* src) {
    asm volatile("cp.async.cg.shared.global [%0], [%1], 16;" :: "r"(dst), "l"(src));
}
__device__ __forceinline__ uint32_t pk(__nv_bfloat16 a, __nv_bfloat16 b) {
    __nv_bfloat162 t;
    t.x = a;   // low 16 bits = element k (even)
    t.y = b;   // high 16 bits = element k+1
    return *(uint32_t*)&t;
}
__device__ __forceinline__ void mma_bf16(float* c, const uint32_t* a, const uint32_t* b) {
    asm volatile(
        "mma.sync.aligned.m16n8k16.row.col.f32.bf16.bf16.f32 "
        "{%0,%1,%2,%3}, {%4,%5,%6,%7}, {%8,%9}, {%0,%1,%2,%3};"
        : "+f"(c[0]), "+f"(c[1]), "+f"(c[2]), "+f"(c[3])
        : "r"(a[0]), "r"(a[1]), "r"(a[2]), "r"(a[3]), "r"(b[0]), "r"(b[1]));
}

// ============================================================================
// C[16384,256] = act(scale * A' @ B'^T), one 128x128 tile per CTA.
//   A': FOLD==4 ? 4-row-group sums of A[65536,K] : A[16384,K]  (fp32 row-major)
//   B'hi/lo: [256, K] bf16 row-major (n-major, k contiguous)
// ============================================================================
template <int FOLD>
__global__ void __launch_bounds__(256, 2)
gemm_mma(const float* __restrict__ A, const __nv_bfloat16* __restrict__ Bhi,
         const __nv_bfloat16* __restrict__ Blo, float* __restrict__ C,
         int ldc, int K, float scale, int do_lrelu) {
    extern __shared__ char smem[];
    const uint32_t sb = smem_u32(smem);
    const int tid = threadIdx.x;
    const int l = tid & 31, wid = tid >> 5;
    const int wm = wid & 1, wn = wid >> 1;       // 2(m) x 4(n) warps, warp 64x32
    const int bn = blockIdx.x, bm = blockIdx.y;  // bn fastest -> L2 A reuse
    const int NK = K >> 5;

    float acc[4][4][4];
#pragma unroll
    for (int mt = 0; mt < 4; mt++)
#pragma unroll
        for (int nt = 0; nt < 4; nt++)
#pragma unroll
            for (int i = 0; i < 4; i++) acc[mt][nt][i] = 0.f;

    auto ldgA = [&](int kc, float4* r) {
        const int k0 = kc << 5;
#pragma unroll
        for (int j = 0; j < 4; j++) {
            const int g = tid + j * 256;             // 1024 float4 granules
            const int row = g >> 3, q = g & 7;
            if (FOLD == 1) {
                r[j] = *(const float4*)(A + (size_t)(bm * 128 + row) * K + k0 + q * 4);
            } else {
                const float4* p = (const float4*)(A + (size_t)(bm * 128 + row) * 4 * K +
                                                  k0 + q * 4);
                const size_t rs = (size_t)K >> 2;
                float4 v0 = p[0], v1 = p[rs], v2 = p[2 * rs], v3 = p[3 * rs];
                float4 v;
                v.x = (v0.x + v1.x) + (v2.x + v3.x);
                v.y = (v0.y + v1.y) + (v2.y + v3.y);
                v.z = (v0.z + v1.z) + (v2.z + v3.z);
                v.w = (v0.w + v1.w) + (v2.w + v3.w);
                r[j] = v;
            }
        }
    };
    auto stsA = [&](const float4* r, int s) {
        char* base = smem + s * STAGE;
#pragma unroll
        for (int j = 0; j < 4; j++) {
            const int g = tid + j * 256;
            const int row = g >> 3, q = g & 7;
            __nv_bfloat16 hx = __float2bfloat16(r[j].x);
            __nv_bfloat16 hy = __float2bfloat16(r[j].y);
            __nv_bfloat16 hz = __float2bfloat16(r[j].z);
            __nv_bfloat16 hw = __float2bfloat16(r[j].w);
            uint2 hi, lo;
            hi.x = pk(hx, hy);
            hi.y = pk(hz, hw);
            lo.x = pk(__float2bfloat16(r[j].x - __bfloat162float(hx)),
                      __float2bfloat16(r[j].y - __bfloat162float(hy)));
            lo.y = pk(__float2bfloat16(r[j].z - __bfloat162float(hz)),
                      __float2bfloat16(r[j].w - __bfloat162float(hw)));
            *(uint2*)(base + OFF_AH + row * 80 + q * 8) = hi;
            *(uint2*)(base + OFF_AL + row * 80 + q * 8) = lo;
        }
    };
    auto fillB = [&](int kc, int s) {
        const int k0 = kc << 5;
#pragma unroll
        for (int j = 0; j < 2; j++) {
            const int g = tid + j * 256;             // 512 granules of 16B (8 bf16)
            const int row = g >> 2, q = g & 3;
            const size_t src = (size_t)(bn * 128 + row) * K + k0 + q * 8;
            const uint32_t so = row * 80 + q * 16;
            cpa16(sb + s * STAGE + OFF_BH + so, Bhi + src);
            cpa16(sb + s * STAGE + OFF_BL + so, Blo + src);
        }
    };

    // prologue
    fillB(0, 0);
    asm volatile("cp.async.commit_group;" ::: "memory");
    {
        float4 a0[4];
        ldgA(0, a0);
        stsA(a0, 0);
    }

    for (int k = 0; k < NK; k++) {
        const int s = k & 1;
        __syncthreads();                             // stage s^1 free
        float4 ar2[4];
        if (k + 1 < NK) {
            fillB(k + 1, s ^ 1);
            asm volatile("cp.async.commit_group;" ::: "memory");
            ldgA(k + 1, ar2);                        // LDGs fly during compute(k)
            asm volatile("cp.async.wait_group 1;" ::: "memory");
        } else {
            asm volatile("cp.async.wait_group 0;" ::: "memory");
        }
        __syncthreads();                             // stage s visible

        const uint32_t* Ah = (const uint32_t*)(smem + s * STAGE + OFF_AH);
        const uint32_t* Al = (const uint32_t*)(smem + s * STAGE + OFF_AL);
        const uint32_t* Bh = (const uint32_t*)(smem + s * STAGE + OFF_BH);
        const uint32_t* Bl = (const uint32_t*)(smem + s * STAGE + OFF_BL);
#pragma unroll
        for (int ks = 0; ks < 2; ks++) {
            const int kw = ks * 8 + (l & 3);
            uint32_t ah[4][4], al[4][4];
#pragma unroll
            for (int mt = 0; mt < 4; mt++) {
                const int r = wm * 64 + mt * 16 + (l >> 2);
                ah[mt][0] = Ah[r * LDW + kw];
                ah[mt][1] = Ah[(r + 8) * LDW + kw];
                ah[mt][2] = Ah[r * LDW + kw + 4];
                ah[mt][3] = Ah[(r + 8) * LDW + kw + 4];
                al[mt][0] = Al[r * LDW + kw];
                al[mt][1] = Al[(r + 8) * LDW + kw];
                al[mt][2] = Al[r * LDW + kw + 4];
                al[mt][3] = Al[(r + 8) * LDW + kw + 4];
            }
#pragma unroll
            for (int nt = 0; nt < 4; nt++) {
                const int n = wn * 32 + nt * 8 + (l >> 2);
                uint32_t bh[2], bl[2];
                bh[0] = Bh[n * LDW + kw];
                bh[1] = Bh[n * LDW + kw + 4];
                bl[0] = Bl[n * LDW + kw];
                bl[1] = Bl[n * LDW + kw + 4];
#pragma unroll
                for (int mt = 0; mt < 4; mt++) {
                    mma_bf16(acc[mt][nt], ah[mt], bh);
                    mma_bf16(acc[mt][nt], al[mt], bh);
                    mma_bf16(acc[mt][nt], ah[mt], bl);
                }
            }
        }
        if (k + 1 < NK) stsA(ar2, s ^ 1);            // hidden under MMA tail
    }

    // epilogue
#pragma unroll
    for (int mt = 0; mt < 4; mt++) {
        const int r0 = bm * 128 + wm * 64 + mt * 16 + (l >> 2);
#pragma unroll
        for (int nt = 0; nt < 4; nt++) {
            const int c0 = bn * 128 + wn * 32 + nt * 8 + 2 * (l & 3);
#pragma unroll
            for (int h = 0; h < 2; h++) {
                float2 v;
                v.x = acc[mt][nt][2 * h + 0] * scale;
                v.y = acc[mt][nt][2 * h + 1] * scale;
                if (do_lrelu) {
                    v.x = (v.x >= 0.f) ? v.x : 0.01f * v.x;
                    v.y = (v.y >= 0.f) ? v.y : 0.01f * v.y;
                }
                *(float2*)(C + (size_t)(r0 + h * 8) * ldc + c0) = v;
            }
        }
    }
}

// [K,256] fp32 -> hi/lo [256,K] bf16 (transpose + exact-residual split)
__global__ void tsplit_bf(const float* __restrict__ in, __nv_bfloat16* __restrict__ hi,
                          __nv_bfloat16* __restrict__ lo, int K) {
    __shared__ float t[32][33];
    const int k0 = blockIdx.x * 32, n0 = blockIdx.y * 32;
    const int tx = threadIdx.x, ty = threadIdx.y;
#pragma unroll
    for (int i = 0; i < 32; i += 8)
        t[ty + i][tx] = in[(size_t)(k0 + ty + i) * 256 + n0 + tx];
    __syncthreads();
#pragma unroll
    for (int i = 0; i < 32; i += 8) {
        const float v = t[tx][ty + i];
        const __nv_bfloat16 h = __float2bfloat16(v);
        const size_t o = (size_t)(n0 + ty + i) * K + k0 + tx;
        hi[o] = h;
        lo[o] = __float2bfloat16(v - __bfloat162float(h));
    }
}

// [256,K] fp32 -> hi/lo bf16 elementwise (W is already n-major)
__global__ void wsplit_bf(const float* __restrict__ in, __nv_bfloat16* __restrict__ hi,
                          __nv_bfloat16* __restrict__ lo) {
    const int i = blockIdx.x * 256 + threadIdx.x;
    const float v = in[i];
    const __nv_bfloat16 h = __float2bfloat16(v);
    hi[i] = h;
    lo[i] = __float2bfloat16(v - __bfloat162float(h));
}

// Acat1[m, 0:256] = feature_matrix[seed[m], :]
__global__ void gatherk(const float4* __restrict__ feat, const int* __restrict__ seed,
                        float4* __restrict__ acat) {
    const int idx = blockIdx.x * 256 + threadIdx.x;   // 16384 * 64
    const int m = idx >> 6, q = idx & 63;
    acat[(size_t)m * 128 + q] = feat[(size_t)seed[m] * 64 + q];
}

extern "C" void kernel_launch(void* const* d_in, const int* in_sizes, int n_in,
                              void* d_out, int out_size) {
    const float* feat = (const float*)d_in[0];   // [100000,256]
    const float* adj1 = (const float*)d_in[1];   // [16384,4096]
    const float* f1 = (const float*)d_in[2];     // [4096,256]
    const float* adj2 = (const float*)d_in[3];   // [65536,2048]
    const float* f2 = (const float*)d_in[4];     // [2048,256]
    const float* W1 = (const float*)d_in[5];     // [256,512]
    const float* W2 = (const float*)d_in[6];     // [256,512]
    const int* seed = (const int*)d_in[7];       // [16384]
    float* out = (float*)d_out;                  // [16384,256]

    float *Acat1, *Acat2;
    __nv_bfloat16 *f1b, *f2b, *W1b, *W2b;
    cudaGetSymbolAddress((void**)&Acat1, g_Acat1);
    cudaGetSymbolAddress((void**)&Acat2, g_Acat2);
    cudaGetSymbolAddress((void**)&f1b, g_f1b);
    cudaGetSymbolAddress((void**)&f2b, g_f2b);
    cudaGetSymbolAddress((void**)&W1b, g_W1b);
    cudaGetSymbolAddress((void**)&W2b, g_W2b);

    cudaFuncSetAttribute(gemm_mma<1>, cudaFuncAttributeMaxDynamicSharedMemorySize, SMEM_TOTAL);
    cudaFuncSetAttribute(gemm_mma<4>, cudaFuncAttributeMaxDynamicSharedMemorySize, SMEM_TOTAL);

    // B-operand bf16 splits (n-major [256, K])
    tsplit_bf<<<dim3(4096 / 32, 8), dim3(32, 8)>>>(f1, f1b, f1b + 256 * 4096, 4096);
    tsplit_bf<<<dim3(2048 / 32, 8), dim3(32, 8)>>>(f2, f2b, f2b + 256 * 2048, 2048);
    wsplit_bf<<<512, 256>>>(W1, W1b, W1b + 256 * 512);
    wsplit_bf<<<512, 256>>>(W2, W2b, W2b + 256 * 512);
    // Acat1[:,0:256] = feat[seed]
    gatherk<<<4096, 256>>>((const float4*)feat, seed, (float4*)Acat1);

    dim3 grid(2, 128), blk(256);
    // Acat1[:,256:512] = 0.5 * adj1 @ f1
    gemm_mma<1><<<grid, blk, SMEM_TOTAL>>>(adj1, f1b, f1b + 256 * 4096,
                                           Acat1 + 256, 512, 4096, 0.5f, 0);
    // Acat2[:,256:512] = 0.125 * fold4(adj2) @ f2
    gemm_mma<4><<<grid, blk, SMEM_TOTAL>>>(adj2, f2b, f2b + 256 * 2048,
                                           Acat2 + 256, 512, 2048, 0.125f, 0);
    // Acat2[:,0:256] = lrelu(Acat1 @ W1^T)
    gemm_mma<1><<<grid, blk, SMEM_TOTAL>>>(Acat1, W1b, W1b + 256 * 512,
                                           Acat2, 512, 512, 1.0f, 1);
    // out = lrelu(Acat2 @ W2^T)
    gemm_mma<1><<<grid, blk, SMEM_TOTAL>>>(Acat2, W2b, W2b + 256 * 512,
                                           out, 256, 512, 1.0f, 1);
}